// round 16
// baseline (speedup 1.0000x reference)
#include <cuda_runtime.h>
#include <cstdint>

#define OBS_D 128
#define HID_D 256
#define ACT_D 32
#define NPOL 64
#define NBATCH 4096
#define MT 128            // batch rows per CTA
#define NTHREADS 256
#define PSTR 528          // activation pair-row stride (u32), === 16 mod 32
#define WPSTR 80          // weight pair-row stride (u32), === 16 mod 32
#define WSTR 40           // layer-4 weight n-row stride (old format)
#define CH_HID (128 * WPSTR)    // 10240 u32 per hidden weight chunk (40KB)
#define CH_OUT (ACT_D * WSTR)   // 1280 u32 per output weight chunk (5KB)

// ---------------- device scratch: transposed tf32 weights, HMMA-fragment-ordered
// hidden layers: per (policy, 32-K chunk): 128 pair-rows (n, n+8) x WPSTR;
//   block at (NP, oct, c): [W(n,k), W(n,k+4), W(n+8,k), W(n+8,k+4)], k=oct*8+c
// layer 4: pair-k format: [n][kl(WSTR)], pos(k)=2*(k&3)+((k>>2)&1)
__device__ uint32_t gW1T[NPOL * 4 * CH_HID];
__device__ uint32_t gW2T[NPOL * 8 * CH_HID];
__device__ uint32_t gW3T[NPOL * 8 * CH_HID];
__device__ uint32_t gW4T[NPOL * 8 * CH_OUT];

// ---------------- helpers
__device__ __forceinline__ uint32_t f2tf32(float f) {
    uint32_t r; asm("cvt.rna.tf32.f32 %0, %1;" : "=r"(r) : "f"(f)); return r;
}
__device__ __forceinline__ void cp_commit() { asm volatile("cp.async.commit_group;"); }
__device__ __forceinline__ void cp_wait0()  { asm volatile("cp.async.wait_group 0;"); }
__device__ __forceinline__ void cp_wait1()  { asm volatile("cp.async.wait_group 1;"); }

__device__ __forceinline__ void cp_chunk(uint32_t* dst, const uint32_t* src, int units) {
    uint32_t d = (uint32_t)__cvta_generic_to_shared(dst);
    for (int u = threadIdx.x; u < units; u += NTHREADS)
        asm volatile("cp.async.cg.shared.global [%0], [%1], 16;"
                     :: "r"(d + (uint32_t)u * 16u), "l"(src + (size_t)u * 4) : "memory");
}

// m16n8k8 tf32 MMA, D += A*B. A quad arrives pre-ordered (one LDS.128).
__device__ __forceinline__ void mma8(float* d, uint32_t a0, uint32_t a1,
                                     uint32_t a2, uint32_t a3,
                                     uint32_t b0, uint32_t b1) {
    asm volatile(
        "mma.sync.aligned.m16n8k8.row.col.f32.tf32.tf32.f32 "
        "{%0,%1,%2,%3}, {%4,%5,%6,%7}, {%8,%9}, {%0,%1,%2,%3};\n"
        : "+f"(d[0]), "+f"(d[1]), "+f"(d[2]), "+f"(d[3])
        : "r"(a0), "r"(a1), "r"(a2), "r"(a3), "r"(b0), "r"(b1));
}

__device__ __forceinline__ float elu(float x) {
    return (x > 0.f) ? x : (__expf(x) - 1.f);
}

// ---------------- merged weight prepass (unchanged from R12)
__global__ void prep_all(const float* __restrict__ W1, const float* __restrict__ W2,
                         const float* __restrict__ W3, const float* __restrict__ W4) {
    __shared__ float s[32 * 256];
    int b = blockIdx.x;
    const float* W; uint32_t* dst; int DOUT, NCH, fmt;
    if (b < 256)       { W = W1; dst = gW1T; DOUT = HID_D; NCH = 4; fmt = 0; }
    else if (b < 768)  { W = W2; dst = gW2T; DOUT = HID_D; NCH = 8; fmt = 0; b -= 256; }
    else if (b < 1280) { W = W3; dst = gW3T; DOUT = HID_D; NCH = 8; fmt = 0; b -= 768; }
    else               { W = W4; dst = gW4T; DOUT = ACT_D; NCH = 8; fmt = 1; b -= 1280; }
    const int p = b / NCH, ch = b % NCH;
    const int DIN = NCH * 32;
    const float* src = W + ((size_t)p * DIN + (size_t)ch * 32) * DOUT;
    for (int i = threadIdx.x; i < 32 * DOUT; i += blockDim.x)
        s[i] = src[i];                       // s[k_local][n]
    __syncthreads();
    if (fmt == 0) {
        uint32_t* o = dst + ((size_t)p * NCH + ch) * CH_HID;
        for (int i = threadIdx.x; i < 128 * WPSTR; i += blockDim.x) {
            int NP = i / WPSTR, q = i % WPSTR;
            uint32_t v = 0;
            if (q < 64) {
                int oct = q >> 4, rem = q & 15, c4 = rem >> 2, pos = rem & 3;
                int wcc = NP >> 5, jj = (NP >> 3) & 3, rr = NP & 7;
                int n  = wcc * 64 + jj * 16 + rr + (pos >> 1) * 8;
                int kl = oct * 8 + c4 + (pos & 1) * 4;
                v = f2tf32(s[kl * DOUT + n]);
            }
            o[i] = v;
        }
    } else {
        uint32_t* o = dst + ((size_t)p * NCH + ch) * CH_OUT;
        for (int i = threadIdx.x; i < DOUT * WSTR; i += blockDim.x) {
            int n = i / WSTR, kl = i % WSTR;
            uint32_t v = 0;
            if (kl < 32) {
                int within = kl & 7;
                int k = (kl & ~7) + ((within & 1) << 2) + (within >> 1);
                v = f2tf32(s[k * DOUT + n]);
            }
            o[i] = v;
        }
    }
}

// ---------------- one hidden layer: acts[128,DIN] @ W[DIN,256] (+bias,GN,ELU)
// 8 warps: rg = wid>>2 (64-row half), wc = wid&3 (64-col group).
// Warp tile 64x64: acc[4 row-blocks][8 n-blocks][4].
template<int NCH>
__device__ __forceinline__ void layer_hidden(
    const uint32_t* wsrc, const uint32_t* nextw, int next_units,
    const float* __restrict__ bias, const float* __restrict__ gam,
    const float* __restrict__ bet,
    uint32_t* actu, uint32_t* wb0, uint32_t* wb1, float* sPar, float2* sRed)
{
    const int tid = threadIdx.x, lane = tid & 31, wid = tid >> 5;
    const int rg = wid >> 2, wc = wid & 3;
    const int r = lane >> 2, c = lane & 3;

    if (tid < HID_D) {
        sPar[tid]       = bias[tid];
        sPar[256 + tid] = gam[tid];
        sPar[512 + tid] = bet[tid];
    }

    const uint32_t* aB[4];
#pragma unroll
    for (int t = 0; t < 4; t++)
        aB[t] = actu + (size_t)((rg * 4 + t) * 8 + r) * PSTR + c * 4;

    float acc[4][8][4];
#pragma unroll
    for (int t = 0; t < 4; t++)
#pragma unroll
        for (int j = 0; j < 8; j++)
#pragma unroll
            for (int q = 0; q < 4; q++) acc[t][j][q] = 0.f;

    for (int ch = 0; ch < NCH; ch++) {
        const uint32_t* wcur = (ch & 1) ? wb1 : wb0;
        if (ch + 1 < NCH) {
            cp_chunk(((ch + 1) & 1) ? wb1 : wb0, wsrc + (size_t)(ch + 1) * CH_HID, CH_HID / 4);
            cp_commit();
            cp_wait1();
        } else {
            cp_wait0();
        }
        __syncthreads();
        const uint32_t* pbB = wcur + (size_t)(wc * 32 + r) * WPSTR + c * 4;
#pragma unroll
        for (int ks = 0; ks < 4; ks++) {
            uint4 a0 = *(const uint4*)(aB[0] + (ch * 4 + ks) * 16);
            uint4 a1 = *(const uint4*)(aB[1] + (ch * 4 + ks) * 16);
            uint4 a2 = *(const uint4*)(aB[2] + (ch * 4 + ks) * 16);
            uint4 a3 = *(const uint4*)(aB[3] + (ch * 4 + ks) * 16);
#pragma unroll
            for (int jj = 0; jj < 4; jj++) {
                uint4 bb = *(const uint4*)(pbB + ks * 16 + jj * 8 * WPSTR);
                mma8(acc[0][2 * jj],     a0.x, a0.y, a0.z, a0.w, bb.x, bb.y);
                mma8(acc[0][2 * jj + 1], a0.x, a0.y, a0.z, a0.w, bb.z, bb.w);
                mma8(acc[1][2 * jj],     a1.x, a1.y, a1.z, a1.w, bb.x, bb.y);
                mma8(acc[1][2 * jj + 1], a1.x, a1.y, a1.z, a1.w, bb.z, bb.w);
                mma8(acc[2][2 * jj],     a2.x, a2.y, a2.z, a2.w, bb.x, bb.y);
                mma8(acc[2][2 * jj + 1], a2.x, a2.y, a2.z, a2.w, bb.z, bb.w);
                mma8(acc[3][2 * jj],     a3.x, a3.y, a3.z, a3.w, bb.x, bb.y);
                mma8(acc[3][2 * jj + 1], a3.x, a3.y, a3.z, a3.w, bb.z, bb.w);
            }
        }
        __syncthreads();   // protect wcur from next iteration's cp.async
    }

    // prefetch next layer's chunk 0 into wb0 (last chunk used wb1; NCH even)
    cp_chunk(wb0, nextw, next_units);
    cp_commit();

    // ---- epilogue: bias + GroupNorm(256) + ELU -> tf32, HMMA-ordered layout
    float s[8], s2[8];
#pragma unroll
    for (int q = 0; q < 8; q++) { s[q] = 0.f; s2[q] = 0.f; }
#pragma unroll
    for (int j = 0; j < 8; j++) {
        const int col = wc * 64 + j * 8 + 2 * c;
        const float bb0 = sPar[col], bb1 = sPar[col + 1];
#pragma unroll
        for (int t = 0; t < 4; t++) {
            float d0 = acc[t][j][0] + bb0;
            float d1 = acc[t][j][1] + bb1;
            float d2 = acc[t][j][2] + bb0;
            float d3 = acc[t][j][3] + bb1;
            acc[t][j][0] = d0; acc[t][j][1] = d1;
            acc[t][j][2] = d2; acc[t][j][3] = d3;
            s[2 * t]     += d0 + d1;  s2[2 * t]     += d0 * d0 + d1 * d1;
            s[2 * t + 1] += d2 + d3;  s2[2 * t + 1] += d2 * d2 + d3 * d3;
        }
    }
#pragma unroll
    for (int q = 0; q < 8; q++) {
        s[q]  += __shfl_xor_sync(0xffffffffu, s[q], 1);
        s2[q] += __shfl_xor_sync(0xffffffffu, s2[q], 1);
        s[q]  += __shfl_xor_sync(0xffffffffu, s[q], 2);
        s2[q] += __shfl_xor_sync(0xffffffffu, s2[q], 2);
    }
    if (c == 0) {
#pragma unroll
        for (int t = 0; t < 4; t++)
#pragma unroll
            for (int h = 0; h < 2; h++)
                sRed[(rg * 64 + t * 16 + h * 8 + r) * 4 + wc] =
                    make_float2(s[2 * t + h], s2[2 * t + h]);
    }
    __syncthreads();
    float mu[8], rs[8];
#pragma unroll
    for (int t = 0; t < 4; t++)
#pragma unroll
        for (int h = 0; h < 2; h++) {
            const int row = rg * 64 + t * 16 + h * 8 + r;
            float2 p0 = sRed[row * 4 + 0], p1 = sRed[row * 4 + 1];
            float2 p2 = sRed[row * 4 + 2], p3 = sRed[row * 4 + 3];
            float S  = p0.x + p1.x + p2.x + p3.x;
            float S2 = p0.y + p1.y + p2.y + p3.y;
            float m  = S * (1.f / HID_D);
            float v  = fmaxf(S2 * (1.f / HID_D) - m * m, 0.f);
            mu[2 * t + h] = m;
            rs[2 * t + h] = rsqrtf(v + 1e-5f);
        }
    const int offE = ((2 * c) & 3) * 4 + (c >> 1) * 2;
    const int offO = ((2 * c + 1) & 3) * 4 + (c >> 1) * 2;
#pragma unroll
    for (int j = 0; j < 8; j++) {
        const int col = wc * 64 + j * 8 + 2 * c;
        const float g0 = sPar[256 + col], e0 = sPar[512 + col];
        const float g1 = sPar[256 + col + 1], e1 = sPar[512 + col + 1];
#pragma unroll
        for (int t = 0; t < 4; t++) {
            float v00 = elu((acc[t][j][0] - mu[2 * t])     * rs[2 * t]     * g0 + e0);
            float v01 = elu((acc[t][j][1] - mu[2 * t])     * rs[2 * t]     * g1 + e1);
            float v10 = elu((acc[t][j][2] - mu[2 * t + 1]) * rs[2 * t + 1] * g0 + e0);
            float v11 = elu((acc[t][j][3] - mu[2 * t + 1]) * rs[2 * t + 1] * g1 + e1);
            uint32_t* dst = actu + (size_t)((rg * 4 + t) * 8 + r) * PSTR
                          + wc * 128 + j * 16;
            *(uint2*)(dst + offE) = make_uint2(f2tf32(v00), f2tf32(v10));
            *(uint2*)(dst + offO) = make_uint2(f2tf32(v01), f2tf32(v11));
        }
    }
    __syncthreads();
}

// ---------------- final layer: acts[128,256] @ W4[256,32] + bias, GN(32) -> out
__device__ __forceinline__ void layer_out(
    const uint32_t* wsrc,
    const float* __restrict__ bias, const float* __restrict__ gam,
    const float* __restrict__ bet,
    uint32_t* actu, uint32_t* wb0, uint32_t* wb1, float* sPar, float2* sRed,
    float* __restrict__ out, int p, int b0)
{
    const int tid = threadIdx.x, lane = tid & 31, wid = tid >> 5;
    const int rg = wid >> 2, wc = wid & 3;
    const int r = lane >> 2, c = lane & 3;

    if (tid < ACT_D) {
        sPar[tid]       = bias[tid];
        sPar[256 + tid] = gam[tid];
        sPar[512 + tid] = bet[tid];
    }

    const uint32_t* aB[4];
#pragma unroll
    for (int t = 0; t < 4; t++)
        aB[t] = actu + (size_t)((rg * 4 + t) * 8 + r) * PSTR + c * 4;

    float acc[4][4];
#pragma unroll
    for (int t = 0; t < 4; t++)
#pragma unroll
        for (int q = 0; q < 4; q++) acc[t][q] = 0.f;

    for (int ch = 0; ch < 8; ch++) {
        const uint32_t* wcur = (ch & 1) ? wb1 : wb0;
        if (ch + 1 < 8) {
            cp_chunk(((ch + 1) & 1) ? wb1 : wb0, wsrc + (size_t)(ch + 1) * CH_OUT, CH_OUT / 4);
            cp_commit();
            cp_wait1();
        } else {
            cp_wait0();
        }
        __syncthreads();
#pragma unroll
        for (int ks = 0; ks < 4; ks++) {
            uint2 bb = *(const uint2*)(wcur + (size_t)(wc * 8 + r) * WSTR + ks * 8 + 2 * c);
#pragma unroll
            for (int t = 0; t < 4; t++) {
                uint4 a = *(const uint4*)(aB[t] + (ch * 4 + ks) * 16);
                mma8(acc[t], a.x, a.y, a.z, a.w, bb.x, bb.y);
            }
        }
        __syncthreads();
    }

    // ---- epilogue: bias + GN over 32 cols -> gmem fp32
    const int col = wc * 8 + 2 * c;
    float s[8], s2[8];
#pragma unroll
    for (int t = 0; t < 4; t++) {
        float d0 = acc[t][0] + sPar[col];
        float d1 = acc[t][1] + sPar[col + 1];
        float d2 = acc[t][2] + sPar[col];
        float d3 = acc[t][3] + sPar[col + 1];
        acc[t][0] = d0; acc[t][1] = d1; acc[t][2] = d2; acc[t][3] = d3;
        s[2 * t]     = d0 + d1;  s2[2 * t]     = d0 * d0 + d1 * d1;
        s[2 * t + 1] = d2 + d3;  s2[2 * t + 1] = d2 * d2 + d3 * d3;
    }
#pragma unroll
    for (int q = 0; q < 8; q++) {
        s[q]  += __shfl_xor_sync(0xffffffffu, s[q], 1);
        s2[q] += __shfl_xor_sync(0xffffffffu, s2[q], 1);
        s[q]  += __shfl_xor_sync(0xffffffffu, s[q], 2);
        s2[q] += __shfl_xor_sync(0xffffffffu, s2[q], 2);
    }
    if (c == 0) {
#pragma unroll
        for (int t = 0; t < 4; t++)
#pragma unroll
            for (int h = 0; h < 2; h++)
                sRed[(rg * 64 + t * 16 + h * 8 + r) * 4 + wc] =
                    make_float2(s[2 * t + h], s2[2 * t + h]);
    }
    __syncthreads();
#pragma unroll
    for (int t = 0; t < 4; t++)
#pragma unroll
        for (int h = 0; h < 2; h++) {
            const int row = rg * 64 + t * 16 + h * 8 + r;
            float2 p0 = sRed[row * 4 + 0], p1 = sRed[row * 4 + 1];
            float2 p2 = sRed[row * 4 + 2], p3 = sRed[row * 4 + 3];
            float S  = p0.x + p1.x + p2.x + p3.x;
            float S2 = p0.y + p1.y + p2.y + p3.y;
            float m  = S * (1.f / ACT_D);
            float v  = fmaxf(S2 * (1.f / ACT_D) - m * m, 0.f);
            float rstd = rsqrtf(v + 1e-5f);
            float2 o;
            o.x = (acc[t][2 * h]     - m) * rstd * sPar[256 + col]     + sPar[512 + col];
            o.y = (acc[t][2 * h + 1] - m) * rstd * sPar[256 + col + 1] + sPar[512 + col + 1];
            *(float2*)(out + (size_t)(b0 + row) * (NPOL * ACT_D) + (size_t)p * ACT_D + col) = o;
        }
}

// ---------------- main fused kernel: CTA = (policy, 128 batch rows)
__global__ void __launch_bounds__(NTHREADS, 1)
mlp_mma_kernel(const float* __restrict__ obs,
               const float* __restrict__ b1, const float* __restrict__ g1, const float* __restrict__ be1,
               const float* __restrict__ b2, const float* __restrict__ g2, const float* __restrict__ be2,
               const float* __restrict__ b3, const float* __restrict__ g3, const float* __restrict__ be3,
               const float* __restrict__ b4, const float* __restrict__ g4, const float* __restrict__ be4,
               float* __restrict__ out)
{
    extern __shared__ float smem[];
    uint32_t* actu = (uint32_t*)smem;                         // 64 * PSTR u32
    uint32_t* wb0  = actu + (size_t)64 * PSTR;                // CH_HID u32
    uint32_t* wb1  = wb0 + CH_HID;                            // CH_HID u32
    float*    sPar = (float*)(wb1 + CH_HID);                  // 768 floats
    float2*   sRed = (float2*)(sPar + 768);                   // 512 float2

    const int tid = threadIdx.x;
    const int p   = blockIdx.y;
    const int b0  = blockIdx.x * MT;
    const size_t pO = (size_t)p;

    // prefetch W1 chunk 0 immediately
    cp_chunk(wb0, gW1T + pO * 4 * CH_HID, CH_HID / 4);
    cp_commit();

    // stage observation tile [128,128] -> tf32, pair-row-interleaved blocks
    for (int i = tid; i < 64 * (OBS_D / 8); i += NTHREADS) {   // 1024 tasks
        int PR = i >> 4, o = i & 15;
        int g = PR >> 3, r = PR & 7;
        const float4* rA = (const float4*)(obs + (size_t)(b0 + g * 16 + r) * OBS_D + o * 8);
        const float4* rB = (const float4*)((const float*)rA + 8 * OBS_D);
        float4 f0 = rA[0], f1 = rA[1];
        float4 f2 = rB[0], f3 = rB[1];
        uint4* d = (uint4*)(actu + (size_t)PR * PSTR + o * 16);
        d[0] = make_uint4(f2tf32(f0.x), f2tf32(f2.x), f2tf32(f1.x), f2tf32(f3.x));
        d[1] = make_uint4(f2tf32(f0.y), f2tf32(f2.y), f2tf32(f1.y), f2tf32(f3.y));
        d[2] = make_uint4(f2tf32(f0.z), f2tf32(f2.z), f2tf32(f1.z), f2tf32(f3.z));
        d[3] = make_uint4(f2tf32(f0.w), f2tf32(f2.w), f2tf32(f1.w), f2tf32(f3.w));
    }
    // visibility: first __syncthreads inside layer_hidden's chunk loop

    layer_hidden<4>(gW1T + pO * 4 * CH_HID, gW2T + pO * 8 * CH_HID, CH_HID / 4,
                    b1 + pO * HID_D, g1 + pO * HID_D, be1 + pO * HID_D,
                    actu, wb0, wb1, sPar, sRed);
    layer_hidden<8>(gW2T + pO * 8 * CH_HID, gW3T + pO * 8 * CH_HID, CH_HID / 4,
                    b2 + pO * HID_D, g2 + pO * HID_D, be2 + pO * HID_D,
                    actu, wb0, wb1, sPar, sRed);
    layer_hidden<8>(gW3T + pO * 8 * CH_HID, gW4T + pO * 8 * CH_OUT, CH_OUT / 4,
                    b3 + pO * HID_D, g3 + pO * HID_D, be3 + pO * HID_D,
                    actu, wb0, wb1, sPar, sRed);
    layer_out(gW4T + pO * 8 * CH_OUT,
              b4 + pO * ACT_D, g4 + pO * ACT_D, be4 + pO * ACT_D,
              actu, wb0, wb1, sPar, sRed, out, p, b0);
}

// ---------------- launch
extern "C" void kernel_launch(void* const* d_in, const int* in_sizes, int n_in,
                              void* d_out, int out_size)
{
    const float* obs = (const float*)d_in[0];
    const float* W1  = (const float*)d_in[1];
    const float* b1  = (const float*)d_in[2];
    const float* g1  = (const float*)d_in[3];
    const float* be1 = (const float*)d_in[4];
    const float* W2  = (const float*)d_in[5];
    const float* b2  = (const float*)d_in[6];
    const float* g2  = (const float*)d_in[7];
    const float* be2 = (const float*)d_in[8];
    const float* W3  = (const float*)d_in[9];
    const float* b3  = (const float*)d_in[10];
    const float* g3  = (const float*)d_in[11];
    const float* be3 = (const float*)d_in[12];
    const float* W4  = (const float*)d_in[13];
    const float* b4  = (const float*)d_in[14];
    const float* g4  = (const float*)d_in[15];
    const float* be4 = (const float*)d_in[16];
    float* out = (float*)d_out;

    // merged prepass: 256 + 512 + 512 + 512 = 1792 chunk-blocks
    prep_all<<<1792, 256>>>(W1, W2, W3, W4);

    const int smem_bytes =
        (64 * PSTR + 2 * CH_HID + 768) * 4 + 512 * 8;   // 224256 B
    cudaFuncSetAttribute(mlp_mma_kernel,
                         cudaFuncAttributeMaxDynamicSharedMemorySize, smem_bytes);

    dim3 grid(NBATCH / MT, NPOL);   // 32 x 64 = 2048 CTAs
    mlp_mma_kernel<<<grid, NTHREADS, smem_bytes>>>(
        obs,
        b1, g1, be1,
        b2, g2, be2,
        b3, g3, be3,
        b4, g4, be4,
        out);
}